// round 2
// baseline (speedup 1.0000x reference)
#include <cuda_runtime.h>

#define BATCH   32
#define NNODES  2000
#define NEDGES  64000
#define EMBED   128
#define ACCW    5      // sum_src_x, sum_src_y, sum_ea_x, sum_ea_y, count
#define CHUNKS  4

// Scratch accumulator: [B][N][5] floats = 1.28 MB (device global, no allocs).
__device__ float g_acc[BATCH * NNODES * ACCW];

__global__ void zero_acc_kernel() {
    int i = blockIdx.x * blockDim.x + threadIdx.x;
    if (i < BATCH * NNODES * ACCW) g_acc[i] = 0.0f;
}

// One block = (chunk of edges) x (one batch). Shared-memory accumulation,
// then atomic merge to global scratch.
__global__ __launch_bounds__(512) void accumulate_kernel(
    const float* __restrict__ locs,      // [B, N, 2]
    const int* __restrict__ edge_index,  // [B, 2, E] int32 (JAX x64 disabled!)
    const float* __restrict__ edge_attr) // [B, E, 2]
{
    __shared__ float s_acc[NNODES * ACCW];   // 40 KB

    const int b     = blockIdx.y;
    const int chunk = blockIdx.x;

    for (int i = threadIdx.x; i < NNODES * ACCW; i += blockDim.x)
        s_acc[i] = 0.0f;
    __syncthreads();

    const int* src_p = edge_index + (long long)b * 2 * NEDGES;
    const int* tgt_p = src_p + NEDGES;
    const float2* ea2  = (const float2*)(edge_attr + (long long)b * NEDGES * 2);
    const float2* loc2 = (const float2*)(locs      + (long long)b * NNODES * 2);

    const int e_per_chunk = NEDGES / CHUNKS;
    const int e0 = chunk * e_per_chunk;
    const int e1 = e0 + e_per_chunk;

    for (int e = e0 + threadIdx.x; e < e1; e += blockDim.x) {
        int srci = src_p[e];
        int tgti = tgt_p[e];
        // Defensive: fail correctness, never fault the device.
        if ((unsigned)srci >= NNODES || (unsigned)tgti >= NNODES) continue;
        float2 xs = loc2[srci];   // gather, L1-resident (16 KB per batch)
        float2 a  = ea2[e];       // coalesced
        float* sp = s_acc + tgti * ACCW;
        atomicAdd(sp + 0, xs.x);
        atomicAdd(sp + 1, xs.y);
        atomicAdd(sp + 2, a.x);
        atomicAdd(sp + 3, a.y);
        atomicAdd(sp + 4, 1.0f);
    }
    __syncthreads();

    float* gp = g_acc + b * NNODES * ACCW;
    for (int i = threadIdx.x; i < NNODES * ACCW; i += blockDim.x) {
        float v = s_acc[i];
        if (v != 0.0f) atomicAdd(gp + i, v);
    }
}

// One thread per output element. Within a warp the node index is uniform
// (embed dim varies fastest) -> acc/locs loads broadcast; W (3 KB) in L1.
__global__ __launch_bounds__(256) void compute_kernel(
    const float* __restrict__ locs,   // [B, N, 2]
    const float* __restrict__ W,      // [128, 6]
    const float* __restrict__ bias,   // [128]
    float* __restrict__ out)          // [B, N, 128]
{
    int idx = blockIdx.x * blockDim.x + threadIdx.x;
    if (idx >= BATCH * NNODES * EMBED) return;

    int d  = idx & (EMBED - 1);
    int bn = idx >> 7;                // b*N + n

    const float* acc = g_acc + bn * ACCW;
    float cnt = acc[4];
    float o = 0.0f;
    if (cnt > 0.0f) {
        float inv = 1.0f / cnt;
        float f0 = locs[(long long)bn * 2 + 0];
        float f1 = locs[(long long)bn * 2 + 1];
        float f2 = acc[0] * inv;
        float f3 = acc[1] * inv;
        float f4 = acc[2] * inv;
        float f5 = acc[3] * inv;
        const float* w = W + d * 6;
        o = bias[d];
        o = fmaf(w[0], f0, o);
        o = fmaf(w[1], f1, o);
        o = fmaf(w[2], f2, o);
        o = fmaf(w[3], f3, o);
        o = fmaf(w[4], f4, o);
        o = fmaf(w[5], f5, o);
    }
    out[idx] = o;
}

extern "C" void kernel_launch(void* const* d_in, const int* in_sizes, int n_in,
                              void* d_out, int out_size) {
    const float* locs       = (const float*)d_in[0];
    const int*   edge_index = (const int*)d_in[1];
    const float* edge_attr  = (const float*)d_in[2];
    const float* W          = (const float*)d_in[3];
    const float* bias       = (const float*)d_in[4];
    float*       out        = (float*)d_out;

    (void)in_sizes; (void)n_in; (void)out_size;

    // 1) zero the scratch accumulator
    zero_acc_kernel<<<(BATCH * NNODES * ACCW + 255) / 256, 256>>>();

    // 2) scatter-accumulate 5-vector per (batch, target node)
    dim3 grid_acc(CHUNKS, BATCH);
    accumulate_kernel<<<grid_acc, 512>>>(locs, edge_index, edge_attr);

    // 3) dense epilogue: out = W @ [x_t, mean_src, mean_ea] + b
    int total = BATCH * NNODES * EMBED;
    compute_kernel<<<(total + 255) / 256, 256>>>(locs, W, bias, out);
}